// round 1
// baseline (speedup 1.0000x reference)
#include <cuda_runtime.h>
#include <cstdint>
#include <cstddef>

#define IN_F   1024
#define OUT_F  1024
#define BATCH  4096
#define NCOEF  8                      // GRID_SIZE + SPLINE_ORDER
#define KTOT   (IN_F + IN_F * NCOEF)  // 9216

// Scratch (allocation-free: __device__ globals)
__device__ float g_A[(size_t)BATCH * KTOT];   // [4096, 9216]  ~151 MB
__device__ float g_B[(size_t)OUT_F * KTOT];   // [1024, 9216]  ~38 MB

// ---------------------------------------------------------------------------
// helpers
// ---------------------------------------------------------------------------
__device__ __forceinline__ float tf32r(float x) {
    uint32_t u;
    asm("cvt.rna.tf32.f32 %0, %1;" : "=r"(u) : "f"(x));
    return __uint_as_float(u);
}

__device__ __forceinline__ void cpa16(uint32_t d, const void* s) {
    asm volatile("cp.async.cg.shared.global [%0], [%1], 16;" :: "r"(d), "l"(s));
}

__device__ __forceinline__ void mma_tf32(float* c, const uint32_t* a, const uint32_t* b) {
    asm volatile(
        "mma.sync.aligned.m16n8k8.row.col.f32.tf32.tf32.f32 "
        "{%0,%1,%2,%3},{%4,%5,%6,%7},{%8,%9},{%0,%1,%2,%3};"
        : "+f"(c[0]), "+f"(c[1]), "+f"(c[2]), "+f"(c[3])
        : "r"(a[0]), "r"(a[1]), "r"(a[2]), "r"(a[3]), "r"(b[0]), "r"(b[1]));
}

// ---------------------------------------------------------------------------
// Prep 1: A[b, 0:1024] = silu(x);  A[b, 1024 + i*8 + j] = basis_j(x[b,i])
// ---------------------------------------------------------------------------
__global__ void build_A(const float* __restrict__ x, const float* __restrict__ grid) {
    int idx = blockIdx.x * blockDim.x + threadIdx.x;   // [0, BATCH*IN_F)
    int b = idx >> 10;
    int i = idx & 1023;

    float xv = x[idx];
    float silu = xv / (1.0f + expf(-xv));

    float g[12];
#pragma unroll
    for (int j = 0; j < 12; j++) g[j] = grid[i * 12 + j];

    float bb[11];
#pragma unroll
    for (int j = 0; j < 11; j++)
        bb[j] = (xv >= g[j] && xv < g[j + 1]) ? 1.0f : 0.0f;

#pragma unroll
    for (int k = 1; k <= 3; k++) {
#pragma unroll
        for (int j = 0; j < 11 - k; j++) {
            bb[j] = (xv - g[j]) / (g[j + k] - g[j] + 1e-8f) * bb[j]
                  + (g[j + k + 1] - xv) / (g[j + k + 1] - g[j + 1] + 1e-8f) * bb[j + 1];
        }
    }

    size_t arow = (size_t)b * KTOT;
    g_A[arow + i] = tf32r(silu);

    float4 v0 = make_float4(tf32r(bb[0]), tf32r(bb[1]), tf32r(bb[2]), tf32r(bb[3]));
    float4 v1 = make_float4(tf32r(bb[4]), tf32r(bb[5]), tf32r(bb[6]), tf32r(bb[7]));
    size_t base = arow + IN_F + (size_t)i * 8;
    *reinterpret_cast<float4*>(&g_A[base])     = v0;
    *reinterpret_cast<float4*>(&g_A[base + 4]) = v1;
}

// ---------------------------------------------------------------------------
// Prep 2: B[o, 0:1024] = base_weight; B[o, 1024 + i*8 + j] = sw[o,i,j]*sc[o,i]
// ---------------------------------------------------------------------------
__global__ void build_B(const float* __restrict__ bw,
                        const float* __restrict__ sw,
                        const float* __restrict__ sc) {
    int idx = blockIdx.x * blockDim.x + threadIdx.x;   // [0, OUT_F*IN_F)
    int o = idx >> 10;
    int i = idx & 1023;

    size_t brow = (size_t)o * KTOT;
    g_B[brow + i] = tf32r(bw[idx]);

    float s = sc[idx];
    const float* swp = sw + (size_t)idx * 8;
    float4 a = *reinterpret_cast<const float4*>(swp);
    float4 c = *reinterpret_cast<const float4*>(swp + 4);

    float4 v0 = make_float4(tf32r(a.x * s), tf32r(a.y * s), tf32r(a.z * s), tf32r(a.w * s));
    float4 v1 = make_float4(tf32r(c.x * s), tf32r(c.y * s), tf32r(c.z * s), tf32r(c.w * s));
    size_t base = brow + IN_F + (size_t)i * 8;
    *reinterpret_cast<float4*>(&g_B[base])     = v0;
    *reinterpret_cast<float4*>(&g_B[base + 4]) = v1;
}

// ---------------------------------------------------------------------------
// GEMM: D[4096,1024] = A @ B^T  (tf32 mma.sync, 128x128x32 tiles, 2-stage)
// ---------------------------------------------------------------------------
#define BM 128
#define BN 128
#define BK 32
#define KS 36          // padded row stride in floats (conflict-free frags)
#define STAGES 2

__global__ __launch_bounds__(256, 2) void gemm_tf32(float* __restrict__ D) {
    extern __shared__ float sm[];
    float* sA = sm;                          // [STAGES][BM][KS]
    float* sB = sm + STAGES * BM * KS;       // [STAGES][BN][KS]

    const uint32_t sbase   = (uint32_t)__cvta_generic_to_shared(sm);
    const uint32_t sBbytes = (uint32_t)(STAGES * BM * KS * 4);

    int tid  = threadIdx.x;
    int warp = tid >> 5, lane = tid & 31;
    int wm = warp >> 2, wn = warp & 3;       // 2 x 4 warp grid
    int bm = blockIdx.y, bn = blockIdx.x;

    const float* Ag = g_A + (size_t)bm * BM * KTOT;
    const float* Bg = g_B + (size_t)bn * BN * KTOT;

    int lr = tid >> 3;            // 0..31 (row base for loads)
    int lc = (tid & 7) * 4;       // float offset within 32-wide k-slice

    float acc[4][4][4];
#pragma unroll
    for (int m = 0; m < 4; m++)
#pragma unroll
        for (int n = 0; n < 4; n++)
#pragma unroll
            for (int q = 0; q < 4; q++) acc[m][n][q] = 0.0f;

    auto loadTile = [&](int kt, int s) {
#pragma unroll
        for (int q = 0; q < 4; q++) {
            int row = lr + q * 32;
            const float* srcA = Ag + (size_t)row * KTOT + kt * BK + lc;
            uint32_t dstA = sbase + (uint32_t)(((s * BM + row) * KS + lc) * 4);
            cpa16(dstA, srcA);
            const float* srcB = Bg + (size_t)row * KTOT + kt * BK + lc;
            uint32_t dstB = sbase + sBbytes + (uint32_t)(((s * BN + row) * KS + lc) * 4);
            cpa16(dstB, srcB);
        }
    };

    const int NT = KTOT / BK;   // 288

    loadTile(0, 0);
    asm volatile("cp.async.commit_group;");

    for (int kt = 0; kt < NT; kt++) {
        int cur = kt & 1;
        if (kt + 1 < NT) {
            loadTile(kt + 1, cur ^ 1);
            asm volatile("cp.async.commit_group;");
            asm volatile("cp.async.wait_group 1;");
        } else {
            asm volatile("cp.async.wait_group 0;");
        }
        __syncthreads();

        const float* As = sA + cur * BM * KS + (wm * 64) * KS;
        const float* Bs = sB + cur * BN * KS + (wn * 32) * KS;

#pragma unroll
        for (int ks = 0; ks < BK / 8; ks++) {
            int kb = ks * 8;
            uint32_t af[4][4];
            uint32_t bf[4][2];
#pragma unroll
            for (int mt = 0; mt < 4; mt++) {
                const float* ap = As + (mt * 16 + (lane >> 2)) * KS + kb + (lane & 3);
                af[mt][0] = __float_as_uint(ap[0]);
                af[mt][1] = __float_as_uint(ap[8 * KS]);
                af[mt][2] = __float_as_uint(ap[4]);
                af[mt][3] = __float_as_uint(ap[8 * KS + 4]);
            }
#pragma unroll
            for (int nt = 0; nt < 4; nt++) {
                const float* bp = Bs + (nt * 8 + (lane >> 2)) * KS + kb + (lane & 3);
                bf[nt][0] = __float_as_uint(bp[0]);
                bf[nt][1] = __float_as_uint(bp[4]);
            }
#pragma unroll
            for (int mt = 0; mt < 4; mt++)
#pragma unroll
                for (int nt = 0; nt < 4; nt++)
                    mma_tf32(acc[mt][nt], af[mt], bf[nt]);
        }
        __syncthreads();
    }

    // Epilogue
    float* Dp = D + (size_t)(bm * BM + wm * 64) * OUT_F + bn * BN + wn * 32;
#pragma unroll
    for (int mt = 0; mt < 4; mt++) {
#pragma unroll
        for (int nt = 0; nt < 4; nt++) {
            int r = mt * 16 + (lane >> 2);
            int c = nt * 8 + (lane & 3) * 2;
            float2 lo = make_float2(acc[mt][nt][0], acc[mt][nt][1]);
            float2 hi = make_float2(acc[mt][nt][2], acc[mt][nt][3]);
            *reinterpret_cast<float2*>(&Dp[(size_t)r * OUT_F + c])       = lo;
            *reinterpret_cast<float2*>(&Dp[(size_t)(r + 8) * OUT_F + c]) = hi;
        }
    }
}

// ---------------------------------------------------------------------------
extern "C" void kernel_launch(void* const* d_in, const int* in_sizes, int n_in,
                              void* d_out, int out_size) {
    const float* x    = (const float*)d_in[0];   // [4096,1024]
    const float* bw   = (const float*)d_in[1];   // [1024,1024]
    const float* sw   = (const float*)d_in[2];   // [1024,1024,8]
    const float* sc   = (const float*)d_in[3];   // [1024,1024]
    const float* grid = (const float*)d_in[4];   // [1024,12]
    float* out = (float*)d_out;                  // [4096,1024]

    build_A<<<(BATCH * IN_F) / 256, 256>>>(x, grid);
    build_B<<<(OUT_F * IN_F) / 256, 256>>>(bw, sw, sc);

    size_t smem = (size_t)STAGES * (BM + BN) * KS * sizeof(float);   // 73728 B
    cudaFuncSetAttribute(gemm_tf32, cudaFuncAttributeMaxDynamicSharedMemorySize, (int)smem);
    dim3 grd(OUT_F / BN, BATCH / BM);   // (8, 32)
    gemm_tf32<<<grd, 256, smem>>>(out);
}

// round 3
// speedup vs baseline: 2.3326x; 2.3326x over previous
#include <cuda_runtime.h>
#include <cuda_fp16.h>
#include <cstdint>
#include <cstddef>

#define IN_F   1024
#define OUT_F  1024
#define BATCH  4096
#define KTOT   9216          // 1024 + 1024*8 (halves per row)
#define BM     128
#define BN     256
#define BK     64            // halves per k-tile (128 B rows)
#define NT     (KTOT / BK)   // 144
#define STAGES 3

// Scratch (allocation-free): fp16
__device__ __half g_A[(size_t)BATCH * KTOT];   // ~75 MB
__device__ __half g_B[(size_t)OUT_F * KTOT];   // ~19 MB

// ---------------------------------------------------------------------------
// helpers
// ---------------------------------------------------------------------------
__device__ __forceinline__ void cpa16(uint32_t d, const void* s) {
    asm volatile("cp.async.cg.shared.global [%0], [%1], 16;" :: "r"(d), "l"(s));
}
__device__ __forceinline__ void ldsm4(uint32_t* r, uint32_t a) {
    asm volatile("ldmatrix.sync.aligned.m8n8.x4.shared.b16 {%0,%1,%2,%3}, [%4];"
                 : "=r"(r[0]), "=r"(r[1]), "=r"(r[2]), "=r"(r[3]) : "r"(a));
}
__device__ __forceinline__ void mma16(float* c, const uint32_t* a, uint32_t b0, uint32_t b1) {
    asm volatile(
        "mma.sync.aligned.m16n8k16.row.col.f32.f16.f16.f32 "
        "{%0,%1,%2,%3},{%4,%5,%6,%7},{%8,%9},{%0,%1,%2,%3};"
        : "+f"(c[0]), "+f"(c[1]), "+f"(c[2]), "+f"(c[3])
        : "r"(a[0]), "r"(a[1]), "r"(a[2]), "r"(a[3]), "r"(b0), "r"(b1));
}
__device__ __forceinline__ uint32_t h2u(__half2 h) {
    return *reinterpret_cast<uint32_t*>(&h);
}

// ---------------------------------------------------------------------------
// Prep A: silu + b-spline basis (division-free de Boor), fp16 out
// ---------------------------------------------------------------------------
__global__ void build_A(const float* __restrict__ x, const float* __restrict__ grid) {
    int idx = blockIdx.x * blockDim.x + threadIdx.x;
    int b = idx >> 10;
    int i = idx & 1023;

    float xv = x[idx];
    float silu = xv / (1.0f + __expf(-xv));

    float g[12];
    const float* gr = grid + i * 12;
#pragma unroll
    for (int j = 0; j < 12; j++) g[j] = gr[j];

    float rk1 = __fdividef(1.0f, g[1] - g[0] + 1e-8f);
    float rk2 = __fdividef(1.0f, g[2] - g[0] + 1e-8f);
    float rk3 = __fdividef(1.0f, g[3] - g[0] + 1e-8f);

    float bb[11];
#pragma unroll
    for (int j = 0; j < 11; j++)
        bb[j] = (xv >= g[j] && xv < g[j + 1]) ? 1.0f : 0.0f;
#pragma unroll
    for (int j = 0; j < 10; j++)
        bb[j] = ((xv - g[j]) * bb[j] + (g[j + 2] - xv) * bb[j + 1]) * rk1;
#pragma unroll
    for (int j = 0; j < 9; j++)
        bb[j] = ((xv - g[j]) * bb[j] + (g[j + 3] - xv) * bb[j + 1]) * rk2;
#pragma unroll
    for (int j = 0; j < 8; j++)
        bb[j] = ((xv - g[j]) * bb[j] + (g[j + 4] - xv) * bb[j + 1]) * rk3;

    size_t arow = (size_t)b * KTOT;
    g_A[arow + i] = __float2half_rn(silu);

    __half2 p0 = __floats2half2_rn(bb[0], bb[1]);
    __half2 p1 = __floats2half2_rn(bb[2], bb[3]);
    __half2 p2 = __floats2half2_rn(bb[4], bb[5]);
    __half2 p3 = __floats2half2_rn(bb[6], bb[7]);
    uint4 v = make_uint4(h2u(p0), h2u(p1), h2u(p2), h2u(p3));
    __stcs(reinterpret_cast<uint4*>(&g_A[arow + IN_F + (size_t)i * 8]), v);
}

// ---------------------------------------------------------------------------
// Prep B
// ---------------------------------------------------------------------------
__global__ void build_B(const float* __restrict__ bw,
                        const float* __restrict__ sw,
                        const float* __restrict__ sc) {
    int idx = blockIdx.x * blockDim.x + threadIdx.x;
    int o = idx >> 10;
    int i = idx & 1023;

    size_t brow = (size_t)o * KTOT;
    g_B[brow + i] = __float2half_rn(bw[idx]);

    float s = sc[idx];
    const float* swp = sw + (size_t)idx * 8;
    float4 a = *reinterpret_cast<const float4*>(swp);
    float4 c = *reinterpret_cast<const float4*>(swp + 4);

    __half2 p0 = __floats2half2_rn(a.x * s, a.y * s);
    __half2 p1 = __floats2half2_rn(a.z * s, a.w * s);
    __half2 p2 = __floats2half2_rn(c.x * s, c.y * s);
    __half2 p3 = __floats2half2_rn(c.z * s, c.w * s);
    uint4 v = make_uint4(h2u(p0), h2u(p1), h2u(p2), h2u(p3));
    *reinterpret_cast<uint4*>(&g_B[brow + IN_F + (size_t)i * 8]) = v;
}

// ---------------------------------------------------------------------------
// GEMM: D[4096,1024] = A @ B^T  (fp16 mma.sync m16n8k16, ldmatrix, 3-stage)
// 512 threads: 16 warps as 2(m) x 8(n), warp tile 64x32
// ---------------------------------------------------------------------------
#define ASTG  (BM * 128)                 // 16384 B per stage
#define BSTG  (BN * 128)                 // 32768 B per stage
#define SM_B  (STAGES * ASTG)            // 49152
#define SMEM_TOT (SM_B + STAGES * BSTG)  // 147456

__global__ __launch_bounds__(512, 1) void gemm_fp16(float* __restrict__ D) {
    extern __shared__ char smem[];
    const uint32_t sb = (uint32_t)__cvta_generic_to_shared(smem);

    int tid = threadIdx.x, wid = tid >> 5, lane = tid & 31;
    int wm = wid >> 3, wn = wid & 7;          // 2 x 8 warps
    const int m_base = wm * 64;
    const int n_base = wn * 32;

    const int c  = tid & 7;                   // 16B chunk in 128B row
    const int r0 = tid >> 3;                  // 0..63
    const __half* Ab = g_A + (size_t)(blockIdx.y * BM) * KTOT + c * 8;
    const __half* Bb = g_B + (size_t)(blockIdx.x * BN) * KTOT + c * 8;

    auto load = [&](int kt, int s) {
        const __half* Ak = Ab + kt * BK;
        const __half* Bk = Bb + kt * BK;
        uint32_t ab = sb + s * ASTG;
        uint32_t bbs = sb + SM_B + s * BSTG;
#pragma unroll
        for (int p = 0; p < 2; p++) {
            int row = r0 + p * 64;
            cpa16(ab + row * 128 + ((c ^ (row & 7)) << 4), Ak + (size_t)row * KTOT);
        }
#pragma unroll
        for (int p = 0; p < 4; p++) {
            int row = r0 + p * 64;
            cpa16(bbs + row * 128 + ((c ^ (row & 7)) << 4), Bk + (size_t)row * KTOT);
        }
        asm volatile("cp.async.commit_group;");
    };

    float acc[4][4][4];
#pragma unroll
    for (int m = 0; m < 4; m++)
#pragma unroll
        for (int n = 0; n < 4; n++)
#pragma unroll
            for (int q = 0; q < 4; q++) acc[m][n][q] = 0.0f;

    load(0, 0);
    load(1, 1);

    int sc_ = 0, sl = 2;
    for (int kt = 0; kt < NT; kt++) {
        if (kt + 2 < NT) {
            load(kt + 2, sl);
            asm volatile("cp.async.wait_group 2;");
        } else if (kt + 1 < NT) {
            asm volatile("cp.async.wait_group 1;");
        } else {
            asm volatile("cp.async.wait_group 0;");
        }
        __syncthreads();

        uint32_t sA = sb + sc_ * ASTG;
        uint32_t sBs = sb + SM_B + sc_ * BSTG;

#pragma unroll
        for (int ks = 0; ks < 4; ks++) {
            int kc = ks * 2 + (lane >> 4);          // chunk for this lane
            uint32_t a[4][4];
#pragma unroll
            for (int mt = 0; mt < 4; mt++) {
                int row = m_base + mt * 16 + (lane & 15);
                ldsm4(a[mt], sA + row * 128 + (((kc ^ (row & 7))) << 4));
            }
            uint32_t bf[2][4];
#pragma unroll
            for (int np = 0; np < 2; np++) {
                int row = n_base + np * 16 + ((lane >> 3) & 1) * 8 + (lane & 7);
                ldsm4(bf[np], sBs + row * 128 + (((kc ^ (row & 7))) << 4));
            }
#pragma unroll
            for (int mt = 0; mt < 4; mt++)
#pragma unroll
                for (int nt = 0; nt < 4; nt++)
                    mma16(acc[mt][nt], a[mt], bf[nt >> 1][nt & 1], bf[nt >> 1][2 + (nt & 1)]);
        }
        __syncthreads();

        sc_ = (sc_ == 2) ? 0 : sc_ + 1;
        sl  = (sl == 2) ? 0 : sl + 1;
    }

    // Epilogue: direct fp32 stores
    float* Dp = D + (size_t)(blockIdx.y * BM + m_base) * OUT_F + blockIdx.x * BN + n_base;
#pragma unroll
    for (int mt = 0; mt < 4; mt++) {
#pragma unroll
        for (int nt = 0; nt < 4; nt++) {
            int r = mt * 16 + (lane >> 2);
            int cc = nt * 8 + (lane & 3) * 2;
            *reinterpret_cast<float2*>(&Dp[(size_t)r * OUT_F + cc]) =
                make_float2(acc[mt][nt][0], acc[mt][nt][1]);
            *reinterpret_cast<float2*>(&Dp[(size_t)(r + 8) * OUT_F + cc]) =
                make_float2(acc[mt][nt][2], acc[mt][nt][3]);
        }
    }
}

// ---------------------------------------------------------------------------
extern "C" void kernel_launch(void* const* d_in, const int* in_sizes, int n_in,
                              void* d_out, int out_size) {
    const float* x    = (const float*)d_in[0];
    const float* bw   = (const float*)d_in[1];
    const float* sw   = (const float*)d_in[2];
    const float* sc   = (const float*)d_in[3];
    const float* grid = (const float*)d_in[4];
    float* out = (float*)d_out;

    build_A<<<(BATCH * IN_F) / 256, 256>>>(x, grid);
    build_B<<<(OUT_F * IN_F) / 256, 256>>>(bw, sw, sc);

    cudaFuncSetAttribute(gemm_fp16, cudaFuncAttributeMaxDynamicSharedMemorySize, SMEM_TOT);
    dim3 grd(OUT_F / BN, BATCH / BM);   // (4, 32)
    gemm_fp16<<<grd, 512, SMEM_TOT>>>(out);
}

// round 4
// speedup vs baseline: 2.4297x; 1.0416x over previous
#include <cuda_runtime.h>
#include <cuda_fp16.h>
#include <cstdint>
#include <cstddef>

#define IN_F   1024
#define OUT_F  1024
#define BATCH  4096
#define KTOT   9216          // halves per row
#define BM     128
#define BN     256
#define BK     64            // halves per k-tile (128 B rows)
#define NT     (KTOT / BK)   // 144
#define STAGES 4

__device__ __half g_A[(size_t)BATCH * KTOT];   // ~75 MB
__device__ __half g_B[(size_t)OUT_F * KTOT];   // ~19 MB

// ---------------------------------------------------------------------------
__device__ __forceinline__ void cpa16(uint32_t d, const void* s) {
    asm volatile("cp.async.cg.shared.global [%0], [%1], 16;" :: "r"(d), "l"(s));
}
__device__ __forceinline__ void ldsm4(uint32_t* r, uint32_t a) {
    asm volatile("ldmatrix.sync.aligned.m8n8.x4.shared.b16 {%0,%1,%2,%3}, [%4];"
                 : "=r"(r[0]), "=r"(r[1]), "=r"(r[2]), "=r"(r[3]) : "r"(a));
}
__device__ __forceinline__ void mma16(float* c, const uint32_t* a, uint32_t b0, uint32_t b1) {
    asm volatile(
        "mma.sync.aligned.m16n8k16.row.col.f32.f16.f16.f32 "
        "{%0,%1,%2,%3},{%4,%5,%6,%7},{%8,%9},{%0,%1,%2,%3};"
        : "+f"(c[0]), "+f"(c[1]), "+f"(c[2]), "+f"(c[3])
        : "r"(a[0]), "r"(a[1]), "r"(a[2]), "r"(a[3]), "r"(b0), "r"(b1));
}
__device__ __forceinline__ uint32_t h2u(__half2 h) {
    return *reinterpret_cast<uint32_t*>(&h);
}

// ---------------------------------------------------------------------------
// Prep A: silu + b-spline basis (division-free de Boor), fp16 out
// ---------------------------------------------------------------------------
__global__ void build_A(const float* __restrict__ x, const float* __restrict__ grid) {
    int idx = blockIdx.x * blockDim.x + threadIdx.x;
    int b = idx >> 10;
    int i = idx & 1023;

    float xv = x[idx];
    float silu = xv / (1.0f + __expf(-xv));

    float g[12];
    const float* gr = grid + i * 12;
#pragma unroll
    for (int j = 0; j < 12; j++) g[j] = gr[j];

    float rk1 = __fdividef(1.0f, g[1] - g[0] + 1e-8f);
    float rk2 = __fdividef(1.0f, g[2] - g[0] + 1e-8f);
    float rk3 = __fdividef(1.0f, g[3] - g[0] + 1e-8f);

    float bb[11];
#pragma unroll
    for (int j = 0; j < 11; j++)
        bb[j] = (xv >= g[j] && xv < g[j + 1]) ? 1.0f : 0.0f;
#pragma unroll
    for (int j = 0; j < 10; j++)
        bb[j] = ((xv - g[j]) * bb[j] + (g[j + 2] - xv) * bb[j + 1]) * rk1;
#pragma unroll
    for (int j = 0; j < 9; j++)
        bb[j] = ((xv - g[j]) * bb[j] + (g[j + 3] - xv) * bb[j + 1]) * rk2;
#pragma unroll
    for (int j = 0; j < 8; j++)
        bb[j] = ((xv - g[j]) * bb[j] + (g[j + 4] - xv) * bb[j + 1]) * rk3;

    size_t arow = (size_t)b * KTOT;
    g_A[arow + i] = __float2half_rn(silu);

    __half2 p0 = __floats2half2_rn(bb[0], bb[1]);
    __half2 p1 = __floats2half2_rn(bb[2], bb[3]);
    __half2 p2 = __floats2half2_rn(bb[4], bb[5]);
    __half2 p3 = __floats2half2_rn(bb[6], bb[7]);
    uint4 v = make_uint4(h2u(p0), h2u(p1), h2u(p2), h2u(p3));
    __stcs(reinterpret_cast<uint4*>(&g_A[arow + IN_F + (size_t)i * 8]), v);
}

// ---------------------------------------------------------------------------
__global__ void build_B(const float* __restrict__ bw,
                        const float* __restrict__ sw,
                        const float* __restrict__ sc) {
    int idx = blockIdx.x * blockDim.x + threadIdx.x;
    int o = idx >> 10;
    int i = idx & 1023;

    size_t brow = (size_t)o * KTOT;
    g_B[brow + i] = __float2half_rn(bw[idx]);

    float s = sc[idx];
    const float* swp = sw + (size_t)idx * 8;
    float4 a = *reinterpret_cast<const float4*>(swp);
    float4 c = *reinterpret_cast<const float4*>(swp + 4);

    __half2 p0 = __floats2half2_rn(a.x * s, a.y * s);
    __half2 p1 = __floats2half2_rn(a.z * s, a.w * s);
    __half2 p2 = __floats2half2_rn(c.x * s, c.y * s);
    __half2 p3 = __floats2half2_rn(c.z * s, c.w * s);
    uint4 v = make_uint4(h2u(p0), h2u(p1), h2u(p2), h2u(p3));
    *reinterpret_cast<uint4*>(&g_B[brow + IN_F + (size_t)i * 8]) = v;
}

// ---------------------------------------------------------------------------
// GEMM: D[4096,1024] = A @ B^T
// 256 threads: 8 warps as 2(m) x 4(n), warp tile 64x64, 4-stage cp.async
// ---------------------------------------------------------------------------
#define ASTG  (BM * 128)                 // 16384 B per stage
#define BSTG  (BN * 128)                 // 32768 B per stage
#define SM_B  (STAGES * ASTG)            // 65536
#define SMEM_TOT (SM_B + STAGES * BSTG)  // 196608

__global__ __launch_bounds__(256, 1) void gemm_fp16(float* __restrict__ D) {
    extern __shared__ char smem[];
    const uint32_t sb = (uint32_t)__cvta_generic_to_shared(smem);

    int tid = threadIdx.x, wid = tid >> 5, lane = tid & 31;
    int wm = wid >> 2, wn = wid & 3;          // 2 x 4 warps
    const int m_base = wm * 64;
    const int n_base = wn * 64;

    const int c  = tid & 7;                   // 16B chunk in 128B row
    const int r0 = tid >> 3;                  // 0..31
    const __half* Ab = g_A + (size_t)(blockIdx.y * BM) * KTOT + c * 8;
    const __half* Bb = g_B + (size_t)(blockIdx.x * BN) * KTOT + c * 8;

    auto load = [&](int kt, int s) {
        const __half* Ak = Ab + kt * BK;
        const __half* Bk = Bb + kt * BK;
        uint32_t ab  = sb + s * ASTG;
        uint32_t bbs = sb + SM_B + s * BSTG;
#pragma unroll
        for (int p = 0; p < 4; p++) {
            int row = r0 + p * 32;
            cpa16(ab + row * 128 + ((c ^ (row & 7)) << 4), Ak + (size_t)row * KTOT);
        }
#pragma unroll
        for (int p = 0; p < 8; p++) {
            int row = r0 + p * 32;
            cpa16(bbs + row * 128 + ((c ^ (row & 7)) << 4), Bk + (size_t)row * KTOT);
        }
        asm volatile("cp.async.commit_group;");
    };

    float acc[4][8][4];
#pragma unroll
    for (int m = 0; m < 4; m++)
#pragma unroll
        for (int n = 0; n < 8; n++)
#pragma unroll
            for (int q = 0; q < 4; q++) acc[m][n][q] = 0.0f;

    load(0, 0);
    load(1, 1);
    load(2, 2);

    for (int kt = 0; kt < NT; kt++) {
        int rem = NT - 1 - kt;
        if (rem >= 2)      asm volatile("cp.async.wait_group 2;");
        else if (rem == 1) asm volatile("cp.async.wait_group 1;");
        else               asm volatile("cp.async.wait_group 0;");
        __syncthreads();   // publishes stage kt, retires reads of stage kt-1

        if (kt + 3 < NT) load(kt + 3, (kt + 3) & (STAGES - 1));

        uint32_t sA  = sb + (kt & (STAGES - 1)) * ASTG;
        uint32_t sBs = sb + SM_B + (kt & (STAGES - 1)) * BSTG;

#pragma unroll
        for (int ks = 0; ks < 4; ks++) {
            int kc = ks * 2 + (lane >> 4);          // 16B chunk for this lane
            uint32_t a[4][4];
#pragma unroll
            for (int mt = 0; mt < 4; mt++) {
                int row = m_base + mt * 16 + (lane & 15);
                ldsm4(a[mt], sA + row * 128 + ((kc ^ (row & 7)) << 4));
            }
            uint32_t bf[4][4];
#pragma unroll
            for (int np = 0; np < 4; np++) {
                int row = n_base + np * 16 + ((lane >> 3) & 1) * 8 + (lane & 7);
                ldsm4(bf[np], sBs + row * 128 + ((kc ^ (row & 7)) << 4));
            }
#pragma unroll
            for (int mt = 0; mt < 4; mt++)
#pragma unroll
                for (int nt = 0; nt < 8; nt++)
                    mma16(acc[mt][nt], a[mt], bf[nt >> 1][nt & 1], bf[nt >> 1][2 + (nt & 1)]);
        }
    }

    // Epilogue
    float* Dp = D + (size_t)(blockIdx.y * BM + m_base) * OUT_F + blockIdx.x * BN + n_base;
#pragma unroll
    for (int mt = 0; mt < 4; mt++) {
#pragma unroll
        for (int nt = 0; nt < 8; nt++) {
            int r  = mt * 16 + (lane >> 2);
            int cc = nt * 8 + (lane & 3) * 2;
            *reinterpret_cast<float2*>(&Dp[(size_t)r * OUT_F + cc]) =
                make_float2(acc[mt][nt][0], acc[mt][nt][1]);
            *reinterpret_cast<float2*>(&Dp[(size_t)(r + 8) * OUT_F + cc]) =
                make_float2(acc[mt][nt][2], acc[mt][nt][3]);
        }
    }
}

// ---------------------------------------------------------------------------
extern "C" void kernel_launch(void* const* d_in, const int* in_sizes, int n_in,
                              void* d_out, int out_size) {
    const float* x    = (const float*)d_in[0];
    const float* bw   = (const float*)d_in[1];
    const float* sw   = (const float*)d_in[2];
    const float* sc   = (const float*)d_in[3];
    const float* grid = (const float*)d_in[4];
    float* out = (float*)d_out;

    build_A<<<(BATCH * IN_F) / 256, 256>>>(x, grid);
    build_B<<<(OUT_F * IN_F) / 256, 256>>>(bw, sw, sc);

    cudaFuncSetAttribute(gemm_fp16, cudaFuncAttributeMaxDynamicSharedMemorySize, SMEM_TOT);
    dim3 grd(OUT_F / BN, BATCH / BM);   // (4, 32)
    gemm_fp16<<<grd, 256, SMEM_TOT>>>(out);
}